// round 12
// baseline (speedup 1.0000x reference)
#include <cuda_runtime.h>
#include <math.h>

// Fixed problem shape
#define BB 8
#define NN 32768
#define CC 4
#define MM 11
#define HALO 10

#define THREADS 256
#define TILE 256                 // outputs(n) per block
#define NTILES (NN / TILE)       // 128
#define VROW 338                 // float4 row stride (skewed max 330)
#define AROW 340                 // float2 row stride; reused as output bounce (>= 1089)

typedef unsigned long long u64;

// Duplicated weight pairs (w,w) as u64, layout [(c*11+j)*6 + d], d = 0..4.
__constant__ u64 c_W[CC * MM * 6];
__device__   u64 g_Wdup[CC * MM * 6];

__device__ __forceinline__ void unpk(u64 v, float& x, float& y) {
    asm("mov.b64 {%0, %1}, %2;" : "=f"(x), "=f"(y) : "l"(v));
}
__device__ __forceinline__ u64 dup2(float x) {
    u64 r; asm("mov.b64 %0, {%1, %1};" : "=l"(r) : "f"(x)); return r;
}
__device__ __forceinline__ u64 ffma2(u64 a, u64 b, u64 c) {
    u64 d; asm("fma.rn.f32x2 %0, %1, %2, %3;" : "=l"(d) : "l"(a), "l"(b), "l"(c)); return d;
}
__device__ __forceinline__ u64 fmul2(u64 a, u64 b) {
    u64 d; asm("mul.rn.f32x2 %0, %1, %2;" : "=l"(d) : "l"(a), "l"(b)); return d;
}
__device__ __forceinline__ int sk4(int e) { return e + (e >> 2); }

__global__ void gmp_prep(const float* __restrict__ W) {
    const int i = threadIdx.x;
    if (i < CC * 5 * MM) {
        const int c = i / 55, r = i % 55, d = r / MM, j = r % MM;
        g_Wdup[(c * MM + j) * 6 + d] = dup2(W[i]);
    }
}

// out[b,c,n] = sum_{j=0..10} z[n-10+j] * P_{c,j}(|z|),  P = w0+w1 a+w2 a^2+w3 a^3+w4 a^4
// sample s <-> n = n0-10+s; entry e holds samples (e, e+1).
// output pair (nl0+2p, nl0+2p+1), tap j uses entry e = nl0 + j + 2p.

__global__ __launch_bounds__(THREADS, 5)
void gmp_fir_kernel(const float* __restrict__ x,
                    float* __restrict__ out)
{
    __shared__ float4 s_v[CC * VROW];      // (re_e, re_{e+1}, im_e, im_{e+1})
    __shared__ float2 s_a[CC * AROW];      // (a_e, a_{e+1}); later reused as output bounce

    const int tile = blockIdx.x % NTILES;
    const int b    = blockIdx.x / NTILES;
    const int n0   = tile * TILE;

    // Stage 2 entries per task from 3 sample loads.
    // Task (t, cp): entries 2t, 2t+1 of channel pair cp; samples 2t, 2t+1, 2t+2.
    const float4* x4 = (const float4*)x + (size_t)b * NN * 2;
    for (int i = threadIdx.x; i < 266; i += THREADS) {
        const int t = i >> 1, cp = i & 1;
        const int e0 = 2 * t;
        const int n  = n0 - HALO + e0;
        float4 v0 = make_float4(0.f, 0.f, 0.f, 0.f);
        float4 v1 = make_float4(0.f, 0.f, 0.f, 0.f);
        float4 v2 = make_float4(0.f, 0.f, 0.f, 0.f);
        if (n >= 0)     v0 = x4[(size_t)n * 2 + cp];
        if (n + 1 >= 0) v1 = x4[(size_t)(n + 1) * 2 + cp];
        const bool has2 = (t <= 131);                  // entry e0+1 <= 264
        if (has2 && n + 2 >= 0) v2 = x4[(size_t)(n + 2) * 2 + cp];

        const float a0x = sqrtf(v0.x * v0.x + v0.y * v0.y);
        const float a0z = sqrtf(v0.z * v0.z + v0.w * v0.w);
        const float a1x = sqrtf(v1.x * v1.x + v1.y * v1.y);
        const float a1z = sqrtf(v1.z * v1.z + v1.w * v1.w);
        const int c0 = 2 * cp, c1 = c0 + 1;
        const int s0 = sk4(e0);
        s_v[c0 * VROW + s0] = make_float4(v0.x, v1.x, v0.y, v1.y);
        s_v[c1 * VROW + s0] = make_float4(v0.z, v1.z, v0.w, v1.w);
        s_a[c0 * AROW + s0] = make_float2(a0x, a1x);
        s_a[c1 * AROW + s0] = make_float2(a0z, a1z);
        if (has2) {
            const float a2x = sqrtf(v2.x * v2.x + v2.y * v2.y);
            const float a2z = sqrtf(v2.z * v2.z + v2.w * v2.w);
            const int s1 = sk4(e0 + 1);
            s_v[c0 * VROW + s1] = make_float4(v1.x, v2.x, v1.y, v2.y);
            s_v[c1 * VROW + s1] = make_float4(v1.z, v2.z, v1.w, v2.w);
            s_a[c0 * AROW + s1] = make_float2(a1x, a2x);
            s_a[c1 * AROW + s1] = make_float2(a1z, a2z);
        }
    }
    __syncthreads();

    // warp -> channel (2 warps per channel); lane-chunk L = 0..63, outputs nl0 = 4L..4L+3.
    const int wid  = threadIdx.x >> 5;
    const int lane = threadIdx.x & 31;
    const int c    = wid & 3;
    const int L    = ((wid >> 2) << 5) + lane;
    const int nl0  = 4 * L;
    const float4* vbase = s_v + c * VROW + 5 * L;   // sk4(4L+off) = 5L + off + (off>>2)
    const float2* abase = s_a + c * AROW + 5 * L;
    const int     wbase = c * (MM * 6);             // warp-uniform constant index
    #define VV(off) vbase[(off) + ((off) >> 2)]
    #define AV(off) (*(const u64*)&abase[(off) + ((off) >> 2)])

    float4 vv[4];
    u64    av[4];
    #pragma unroll
    for (int u = 0; u < 3; ++u) { vv[u] = VV(u); av[u] = AV(u); }

    u64 accR0 = 0ull, accR1 = 0ull, accI0 = 0ull, accI1 = 0ull;

    #pragma unroll
    for (int j = 0; j < MM; ++j) {
        if (j < MM - 1) {
            vv[(j + 3) & 3] = VV(j + 3);
            av[(j + 3) & 3] = AV(j + 3);
        }
        const u64 W0 = c_W[wbase + j * 6 + 0];   // uniform constant-port loads
        const u64 W1 = c_W[wbase + j * 6 + 1];
        const u64 W2 = c_W[wbase + j * 6 + 2];
        const u64 W3 = c_W[wbase + j * 6 + 3];
        const u64 W4 = c_W[wbase + j * 6 + 4];

        {   // pair p=0: entry j -> outputs nl0, nl0+1
            const float4& V = vv[j & 3];
            const u64 aa = av[j & 3];
            const u64 a2 = fmul2(aa, aa);
            u64 t = ffma2(aa, W1, W0);
            u64 q = ffma2(aa, W3, W2);
            q = ffma2(a2, W4, q);
            const u64 P = ffma2(a2, q, t);
            accR0 = ffma2(*(const u64*)&V.x, P, accR0);
            accI0 = ffma2(*(const u64*)&V.z, P, accI0);
        }
        {   // pair p=1: entry j+2 -> outputs nl0+2, nl0+3
            const float4& V = vv[(j + 2) & 3];
            const u64 aa = av[(j + 2) & 3];
            const u64 a2 = fmul2(aa, aa);
            u64 t = ffma2(aa, W1, W0);
            u64 q = ffma2(aa, W3, W2);
            q = ffma2(a2, W4, q);
            const u64 P = ffma2(a2, q, t);
            accR1 = ffma2(*(const u64*)&V.x, P, accR1);
            accI1 = ffma2(*(const u64*)&V.z, P, accI1);
        }
    }
    #undef VV
    #undef AV

    // Bounce through smem (reuse s_a) for coalesced global stores.
    __syncthreads();
    {
        float r0, r1, i0, i1;
        unpk(accR0, r0, r1); unpk(accI0, i0, i1);
        int e;
        e = (nl0 + 0) * CC + c; s_a[e + (e >> 5)] = make_float2(r0, i0);
        e = (nl0 + 1) * CC + c; s_a[e + (e >> 5)] = make_float2(r1, i1);
        unpk(accR1, r0, r1); unpk(accI1, i0, i1);
        e = (nl0 + 2) * CC + c; s_a[e + (e >> 5)] = make_float2(r0, i0);
        e = (nl0 + 3) * CC + c; s_a[e + (e >> 5)] = make_float2(r1, i1);
    }
    __syncthreads();

    float2* o2 = (float2*)out + ((size_t)b * NN + n0) * CC;
    #pragma unroll
    for (int t = 0; t < (TILE * CC) / THREADS; ++t) {
        const int i = threadIdx.x + t * THREADS;
        o2[i] = s_a[i + (i >> 5)];
    }
}

extern "C" void kernel_launch(void* const* d_in, const int* in_sizes, int n_in,
                              void* d_out, int out_size)
{
    const float* x = (const float*)d_in[0];   // [B,N,C,2] fp32
    const float* W = (const float*)d_in[1];   // [C, 55]   fp32
    float* out = (float*)d_out;               // [B,N,C,2] fp32
    (void)in_sizes; (void)n_in; (void)out_size;

    // 1) pack duplicated weight pairs into a device staging array
    gmp_prep<<<1, 224>>>(W);
    // 2) D2D async copy into the constant bank (graph-capturable memcpy node)
    void* src = nullptr;
    cudaGetSymbolAddress(&src, g_Wdup);
    cudaMemcpyToSymbolAsync(c_W, src, sizeof(u64) * CC * MM * 6, 0,
                            cudaMemcpyDeviceToDevice, 0);
    // 3) main kernel
    gmp_fir_kernel<<<BB * NTILES, THREADS>>>(x, out);
}

// round 13
// speedup vs baseline: 1.0288x; 1.0288x over previous
#include <cuda_runtime.h>
#include <math.h>

// Fixed problem shape
#define BB 8
#define NN 32768
#define CC 4
#define MM 11
#define HALO 10

#define THREADS 256
#define TILE 256                 // outputs(n) per tile
#define NTILES (NN / TILE)       // 128
#define TOTTILES (BB * NTILES)   // 1024
#define GRID 740                 // 5 CTAs x 148 SMs: one resident wave
#define VROW 338                 // float4 row stride (skewed max 330)
#define AROW 340                 // float2 row stride; reused as output bounce

typedef unsigned long long u64;
struct uu2 { u64 x, y; };

__device__ __forceinline__ void unpk(u64 v, float& x, float& y) {
    asm("mov.b64 {%0, %1}, %2;" : "=f"(x), "=f"(y) : "l"(v));
}
__device__ __forceinline__ u64 ffma2(u64 a, u64 b, u64 c) {
    u64 d; asm("fma.rn.f32x2 %0, %1, %2, %3;" : "=l"(d) : "l"(a), "l"(b), "l"(c)); return d;
}
__device__ __forceinline__ u64 fmul2(u64 a, u64 b) {
    u64 d; asm("mul.rn.f32x2 %0, %1, %2;" : "=l"(d) : "l"(a), "l"(b)); return d;
}
__device__ __forceinline__ int sk4(int e) { return e + (e >> 2); }

// out[b,c,n] = sum_{j=0..10} z[n-10+j] * P_{c,j}(|z|),  P = w0+w1 a+w2 a^2+w3 a^3+w4 a^4
// sample s <-> n = n0-10+s; entry e holds samples (e, e+1).
// output pair (nl0+2p, nl0+2p+1), tap j uses entry e = nl0 + j + 2p.

__global__ __launch_bounds__(THREADS, 5)
void gmp_fir_kernel(const float* __restrict__ x,
                    const float* __restrict__ W,
                    float* __restrict__ out)
{
    __shared__ float4 s_v[CC * VROW];           // (re_e, re_{e+1}, im_e, im_{e+1})
    __shared__ float2 s_a[CC * AROW];           // (a_e, a_{e+1}); reused as output bounce
    __shared__ __align__(16) float2 s_W2[CC * MM * 6];   // duplicated (w,w) pairs, stride 6

    // Stage weights once per block: W[c, d*11+j] -> s_W2[(c*11+j)*6 + d]
    for (int i = threadIdx.x; i < CC * 5 * MM; i += THREADS) {
        const int c = i / 55, r = i % 55, d = r / MM, j = r % MM;
        const float w = W[i];
        s_W2[(c * MM + j) * 6 + d] = make_float2(w, w);
    }

    // Per-thread invariants
    const int wid  = threadIdx.x >> 5;
    const int lane = threadIdx.x & 31;
    const int c    = wid & 3;
    const int L    = ((wid >> 2) << 5) + lane;  // 0..63
    const int nl0  = 4 * L;
    const float4* vbase = s_v + c * VROW + 5 * L;   // sk4(4L+off) = 5L + off + (off>>2)
    const float2* abase = s_a + c * AROW + 5 * L;
    const float2* wrow  = s_W2 + c * (MM * 6);
    #define VV(off) vbase[(off) + ((off) >> 2)]
    #define AV(off) (*(const u64*)&abase[(off) + ((off) >> 2)])

    const int nrep = (blockIdx.x < TOTTILES - GRID) ? 2 : 1;   // first 284 blocks do 2 tiles

    for (int rep = 0; rep < nrep; ++rep) {
        const int t    = blockIdx.x + rep * GRID;
        const int b    = t >> 7;            // t / 128
        const int n0   = (t & 127) * TILE;

        if (rep) __syncthreads();           // prior epilogue reads of s_a complete

        // Stage 2 entries per task from 3 sample loads.
        const float4* x4 = (const float4*)x + (size_t)b * NN * 2;
        for (int i = threadIdx.x; i < 266; i += THREADS) {
            const int tt = i >> 1, cp = i & 1;
            const int e0 = 2 * tt;
            const int n  = n0 - HALO + e0;
            float4 v0 = make_float4(0.f, 0.f, 0.f, 0.f);
            float4 v1 = make_float4(0.f, 0.f, 0.f, 0.f);
            float4 v2 = make_float4(0.f, 0.f, 0.f, 0.f);
            if (n >= 0)     v0 = x4[(size_t)n * 2 + cp];
            if (n + 1 >= 0) v1 = x4[(size_t)(n + 1) * 2 + cp];
            const bool has2 = (tt <= 131);             // entry e0+1 <= 264
            if (has2 && n + 2 >= 0) v2 = x4[(size_t)(n + 2) * 2 + cp];

            const float a0x = sqrtf(v0.x * v0.x + v0.y * v0.y);
            const float a0z = sqrtf(v0.z * v0.z + v0.w * v0.w);
            const float a1x = sqrtf(v1.x * v1.x + v1.y * v1.y);
            const float a1z = sqrtf(v1.z * v1.z + v1.w * v1.w);
            const int c0 = 2 * cp, c1 = c0 + 1;
            const int s0 = sk4(e0);
            s_v[c0 * VROW + s0] = make_float4(v0.x, v1.x, v0.y, v1.y);
            s_v[c1 * VROW + s0] = make_float4(v0.z, v1.z, v0.w, v1.w);
            s_a[c0 * AROW + s0] = make_float2(a0x, a1x);
            s_a[c1 * AROW + s0] = make_float2(a0z, a1z);
            if (has2) {
                const float a2x = sqrtf(v2.x * v2.x + v2.y * v2.y);
                const float a2z = sqrtf(v2.z * v2.z + v2.w * v2.w);
                const int s1 = sk4(e0 + 1);
                s_v[c0 * VROW + s1] = make_float4(v1.x, v2.x, v1.y, v2.y);
                s_v[c1 * VROW + s1] = make_float4(v1.z, v2.z, v1.w, v2.w);
                s_a[c0 * AROW + s1] = make_float2(a1x, a2x);
                s_a[c1 * AROW + s1] = make_float2(a1z, a2z);
            }
        }
        __syncthreads();

        float4 vv[4];
        u64    av[4];
        #pragma unroll
        for (int u = 0; u < 3; ++u) { vv[u] = VV(u); av[u] = AV(u); }

        u64 accR0 = 0ull, accR1 = 0ull, accI0 = 0ull, accI1 = 0ull;

        #pragma unroll
        for (int j = 0; j < MM; ++j) {
            if (j < MM - 1) {
                vv[(j + 3) & 3] = VV(j + 3);
                av[(j + 3) & 3] = AV(j + 3);
            }
            const uu2 wAB = *(const uu2*)&wrow[j * 6 + 0];   // (W0, W1)
            const uu2 wCD = *(const uu2*)&wrow[j * 6 + 2];   // (W2, W3)
            const u64 W4  = *(const u64*)&wrow[j * 6 + 4];

            {   // pair p=0: entry j -> outputs nl0, nl0+1
                const float4& V = vv[j & 3];
                const u64 aa = av[j & 3];
                const u64 a2 = fmul2(aa, aa);
                u64 tt = ffma2(aa, wAB.y, wAB.x);
                u64 q  = ffma2(aa, wCD.y, wCD.x);
                q = ffma2(a2, W4, q);
                const u64 P = ffma2(a2, q, tt);
                accR0 = ffma2(*(const u64*)&V.x, P, accR0);
                accI0 = ffma2(*(const u64*)&V.z, P, accI0);
            }
            {   // pair p=1: entry j+2 -> outputs nl0+2, nl0+3
                const float4& V = vv[(j + 2) & 3];
                const u64 aa = av[(j + 2) & 3];
                const u64 a2 = fmul2(aa, aa);
                u64 tt = ffma2(aa, wAB.y, wAB.x);
                u64 q  = ffma2(aa, wCD.y, wCD.x);
                q = ffma2(a2, W4, q);
                const u64 P = ffma2(a2, q, tt);
                accR1 = ffma2(*(const u64*)&V.x, P, accR1);
                accI1 = ffma2(*(const u64*)&V.z, P, accI1);
            }
        }

        // Bounce through smem (reuse s_a) for coalesced global stores.
        __syncthreads();
        {
            float r0, r1, i0, i1;
            unpk(accR0, r0, r1); unpk(accI0, i0, i1);
            int e;
            e = (nl0 + 0) * CC + c; s_a[e + (e >> 5)] = make_float2(r0, i0);
            e = (nl0 + 1) * CC + c; s_a[e + (e >> 5)] = make_float2(r1, i1);
            unpk(accR1, r0, r1); unpk(accI1, i0, i1);
            e = (nl0 + 2) * CC + c; s_a[e + (e >> 5)] = make_float2(r0, i0);
            e = (nl0 + 3) * CC + c; s_a[e + (e >> 5)] = make_float2(r1, i1);
        }
        __syncthreads();

        float2* o2 = (float2*)out + ((size_t)b * NN + n0) * CC;
        #pragma unroll
        for (int u = 0; u < (TILE * CC) / THREADS; ++u) {
            const int i = threadIdx.x + u * THREADS;
            o2[i] = s_a[i + (i >> 5)];
        }
    }
    #undef VV
    #undef AV
}

extern "C" void kernel_launch(void* const* d_in, const int* in_sizes, int n_in,
                              void* d_out, int out_size)
{
    const float* x = (const float*)d_in[0];   // [B,N,C,2] fp32
    const float* W = (const float*)d_in[1];   // [C, 55]   fp32
    float* out = (float*)d_out;               // [B,N,C,2] fp32
    (void)in_sizes; (void)n_in; (void)out_size;

    gmp_fir_kernel<<<GRID, THREADS>>>(x, W, out);
}

// round 14
// speedup vs baseline: 1.1400x; 1.1081x over previous
#include <cuda_runtime.h>
#include <math.h>

// Fixed problem shape
#define BB 8
#define NN 32768
#define CC 4
#define MM 11
#define HALO 10

#define THREADS 256
#define TILE 256                 // outputs(n) per block
#define NTILES (NN / TILE)       // 128
#define VROW 338                 // float4 row stride (skewed max 330)
#define AROW 338                 // float2 row stride
#define OUTB (TILE * CC + 33)    // output bounce (skewed 1024 float2)

typedef unsigned long long u64;
struct uu2 { u64 x, y; };

__device__ __forceinline__ void unpk(u64 v, float& x, float& y) {
    asm("mov.b64 {%0, %1}, %2;" : "=f"(x), "=f"(y) : "l"(v));
}
__device__ __forceinline__ u64 ffma2(u64 a, u64 b, u64 c) {
    u64 d; asm("fma.rn.f32x2 %0, %1, %2, %3;" : "=l"(d) : "l"(a), "l"(b), "l"(c)); return d;
}
__device__ __forceinline__ u64 fmul2(u64 a, u64 b) {
    u64 d; asm("mul.rn.f32x2 %0, %1, %2;" : "=l"(d) : "l"(a), "l"(b)); return d;
}
__device__ __forceinline__ float sqrt_ap(float q) {   // 1x MUFU, ~2^-21 rel err (budget 1e-3)
    float r; asm("sqrt.approx.f32 %0, %1;" : "=f"(r) : "f"(q)); return r;
}
__device__ __forceinline__ int sk4(int e) { return e + (e >> 2); }

// out[b,c,n] = sum_{j=0..10} z[n-10+j] * P_{c,j}(|z|),  P = w0+w1 a+w2 a^2+w3 a^3+w4 a^4
// sample s <-> n = n0-10+s; entry e holds samples (e, e+1).
// output pair (nl0+2p, nl0+2p+1), tap j uses entry e = nl0 + j + 2p.

__global__ __launch_bounds__(THREADS, 5)
void gmp_fir_kernel(const float* __restrict__ x,
                    const float* __restrict__ W,
                    float* __restrict__ out)
{
    __shared__ float4 s_v[CC * VROW];      // (re_e, re_{e+1}, im_e, im_{e+1})
    __shared__ float2 s_a[CC * AROW];      // (a_e, a_{e+1})
    __shared__ float2 s_o[OUTB];           // output bounce (separate -> one less barrier)
    __shared__ __align__(16) float2 s_W2[CC * MM * 6];   // duplicated (w,w) pairs

    const int tile = blockIdx.x % NTILES;
    const int b    = blockIdx.x / NTILES;
    const int n0   = tile * TILE;

    // Weights: W[c, d*11+j] -> s_W2[(c*11+j)*6 + d] = (w, w)
    for (int i = threadIdx.x; i < CC * 5 * MM; i += THREADS) {
        const int c = i / 55, r = i % 55, d = r / MM, j = r % MM;
        const float w = W[i];
        s_W2[(c * MM + j) * 6 + d] = make_float2(w, w);
    }

    // Stage 2 entries per task from 3 sample loads.
    // Task (t, cp): entries 2t, 2t+1 of channel pair cp; samples 2t, 2t+1, 2t+2.
    const float4* x4 = (const float4*)x + (size_t)b * NN * 2;
    for (int i = threadIdx.x; i < 266; i += THREADS) {
        const int t = i >> 1, cp = i & 1;
        const int e0 = 2 * t;
        const int n  = n0 - HALO + e0;
        float4 v0 = make_float4(0.f, 0.f, 0.f, 0.f);
        float4 v1 = make_float4(0.f, 0.f, 0.f, 0.f);
        float4 v2 = make_float4(0.f, 0.f, 0.f, 0.f);
        if (n >= 0)     v0 = x4[(size_t)n * 2 + cp];
        if (n + 1 >= 0) v1 = x4[(size_t)(n + 1) * 2 + cp];
        const bool has2 = (t <= 131);                  // entry e0+1 <= 264
        if (has2 && n + 2 >= 0) v2 = x4[(size_t)(n + 2) * 2 + cp];

        const float a0x = sqrt_ap(v0.x * v0.x + v0.y * v0.y);
        const float a0z = sqrt_ap(v0.z * v0.z + v0.w * v0.w);
        const float a1x = sqrt_ap(v1.x * v1.x + v1.y * v1.y);
        const float a1z = sqrt_ap(v1.z * v1.z + v1.w * v1.w);
        const int c0 = 2 * cp, c1 = c0 + 1;
        const int s0 = sk4(e0);
        s_v[c0 * VROW + s0] = make_float4(v0.x, v1.x, v0.y, v1.y);
        s_v[c1 * VROW + s0] = make_float4(v0.z, v1.z, v0.w, v1.w);
        s_a[c0 * AROW + s0] = make_float2(a0x, a1x);
        s_a[c1 * AROW + s0] = make_float2(a0z, a1z);
        if (has2) {
            const float a2x = sqrt_ap(v2.x * v2.x + v2.y * v2.y);
            const float a2z = sqrt_ap(v2.z * v2.z + v2.w * v2.w);
            const int s1 = sk4(e0 + 1);
            s_v[c0 * VROW + s1] = make_float4(v1.x, v2.x, v1.y, v2.y);
            s_v[c1 * VROW + s1] = make_float4(v1.z, v2.z, v1.w, v2.w);
            s_a[c0 * AROW + s1] = make_float2(a1x, a2x);
            s_a[c1 * AROW + s1] = make_float2(a1z, a2z);
        }
    }
    __syncthreads();

    // warp -> channel (2 warps per channel); lane-chunk L = 0..63, outputs nl0 = 4L..4L+3.
    const int wid  = threadIdx.x >> 5;
    const int lane = threadIdx.x & 31;
    const int c    = wid & 3;
    const int L    = ((wid >> 2) << 5) + lane;
    const int nl0  = 4 * L;
    const float4* vbase = s_v + c * VROW + 5 * L;   // sk4(4L+off) = 5L + off + (off>>2)
    const float2* abase = s_a + c * AROW + 5 * L;
    const float2* wrow  = s_W2 + c * (MM * 6);
    #define VV(off) vbase[(off) + ((off) >> 2)]
    #define AV(off) (*(const u64*)&abase[(off) + ((off) >> 2)])

    float4 vv[4];
    u64    av[4];
    #pragma unroll
    for (int u = 0; u < 3; ++u) { vv[u] = VV(u); av[u] = AV(u); }

    u64 accR0 = 0ull, accR1 = 0ull, accI0 = 0ull, accI1 = 0ull;

    #pragma unroll
    for (int j = 0; j < MM; ++j) {
        if (j < MM - 1) {
            vv[(j + 3) & 3] = VV(j + 3);
            av[(j + 3) & 3] = AV(j + 3);
        }
        const uu2 wAB = *(const uu2*)&wrow[j * 6 + 0];   // (W0, W1)
        const uu2 wCD = *(const uu2*)&wrow[j * 6 + 2];   // (W2, W3)
        const u64 W4  = *(const u64*)&wrow[j * 6 + 4];

        {   // pair p=0: entry j -> outputs nl0, nl0+1
            const float4& V = vv[j & 3];
            const u64 aa = av[j & 3];
            const u64 a2 = fmul2(aa, aa);
            u64 t = ffma2(aa, wAB.y, wAB.x);
            u64 q = ffma2(aa, wCD.y, wCD.x);
            q = ffma2(a2, W4, q);
            const u64 P = ffma2(a2, q, t);
            accR0 = ffma2(*(const u64*)&V.x, P, accR0);
            accI0 = ffma2(*(const u64*)&V.z, P, accI0);
        }
        {   // pair p=1: entry j+2 -> outputs nl0+2, nl0+3
            const float4& V = vv[(j + 2) & 3];
            const u64 aa = av[(j + 2) & 3];
            const u64 a2 = fmul2(aa, aa);
            u64 t = ffma2(aa, wAB.y, wAB.x);
            u64 q = ffma2(aa, wCD.y, wCD.x);
            q = ffma2(a2, W4, q);
            const u64 P = ffma2(a2, q, t);
            accR1 = ffma2(*(const u64*)&V.x, P, accR1);
            accI1 = ffma2(*(const u64*)&V.z, P, accI1);
        }
    }
    #undef VV
    #undef AV

    // Write packed results into the dedicated bounce buffer (no barrier needed first).
    {
        float r0, r1, i0, i1;
        unpk(accR0, r0, r1); unpk(accI0, i0, i1);
        int e;
        e = (nl0 + 0) * CC + c; s_o[e + (e >> 5)] = make_float2(r0, i0);
        e = (nl0 + 1) * CC + c; s_o[e + (e >> 5)] = make_float2(r1, i1);
        unpk(accR1, r0, r1); unpk(accI1, i0, i1);
        e = (nl0 + 2) * CC + c; s_o[e + (e >> 5)] = make_float2(r0, i0);
        e = (nl0 + 3) * CC + c; s_o[e + (e >> 5)] = make_float2(r1, i1);
    }
    __syncthreads();

    float2* o2 = (float2*)out + ((size_t)b * NN + n0) * CC;
    #pragma unroll
    for (int t = 0; t < (TILE * CC) / THREADS; ++t) {
        const int i = threadIdx.x + t * THREADS;
        o2[i] = s_o[i + (i >> 5)];
    }
}

extern "C" void kernel_launch(void* const* d_in, const int* in_sizes, int n_in,
                              void* d_out, int out_size)
{
    const float* x = (const float*)d_in[0];   // [B,N,C,2] fp32
    const float* W = (const float*)d_in[1];   // [C, 55]   fp32
    float* out = (float*)d_out;               // [B,N,C,2] fp32
    (void)in_sizes; (void)n_in; (void)out_size;

    gmp_fir_kernel<<<BB * NTILES, THREADS>>>(x, W, out);
}